// round 15
// baseline (speedup 1.0000x reference)
#include <cuda_runtime.h>
#include <cuda_bf16.h>
#include <cstdint>

#define NROWS 16384
#define DIM   1024
#define NCENT 1024
#define MARGIN 0.35f

#define BM 128
#define BN 128
#define BK 32
#define PAD_K 40   // bf16 elems per smem row (80B stride -> conflict-free ldmatrix)
#define NITER (DIM / BK)
#define NGRP  (NCENT / 64)   // 16 col-groups of 64 per row
#define MAXCAND 64

// ---- scratch (device globals only; no runtime allocation allowed) ----
__device__ float              g_csq[NCENT];
__device__ float              g_tmin[(size_t)NROWS * NGRP];   // 1 MB
__device__ unsigned long long g_mask[(size_t)NROWS * NGRP];   // 2 MB
__device__ __nv_bfloat16      g_xb[(size_t)NROWS * DIM];      // 32 MB
__device__ __nv_bfloat16      g_cb[(size_t)NCENT * DIM];      //  2 MB

// ---------------------------------------------------------------------------
// Prep, warp-per-row: 8 rows per 256-thread block, no block barriers.
// Loads batched first (MLP=8/thread), then convert+store. csq only needed
// for centroids (x_sq is recomputed in the rescore slow path).
// ---------------------------------------------------------------------------
__global__ __launch_bounds__(256) void prep_kernel(
    const float* __restrict__ x, const float* __restrict__ c)
{
    const int w = threadIdx.x >> 5, lane = threadIdx.x & 31;
    const int row = blockIdx.x * 8 + w;
    const bool isX = (row < NROWS);
    const int r = isX ? row : (row - NROWS);
    const float4* src = (const float4*)((isX ? x : c) + (size_t)r * DIM);
    __nv_bfloat162* dst = (__nv_bfloat162*)((isX ? g_xb : g_cb) + (size_t)r * DIM);

    float4 v[8];
    #pragma unroll
    for (int j = 0; j < 8; j++) v[j] = src[j * 32 + lane];   // 8 LDG.128 in flight

    float acc = 0.f;
    #pragma unroll
    for (int j = 0; j < 8; j++) {
        const int e = j * 32 + lane;
        __nv_bfloat162 b01, b23;
        b01.x = __float2bfloat16(v[j].x); b01.y = __float2bfloat16(v[j].y);
        b23.x = __float2bfloat16(v[j].z); b23.y = __float2bfloat16(v[j].w);
        dst[e * 2 + 0] = b01;
        dst[e * 2 + 1] = b23;
        acc = fmaf(v[j].x, v[j].x, acc);
        acc = fmaf(v[j].y, v[j].y, acc);
        acc = fmaf(v[j].z, v[j].z, acc);
        acc = fmaf(v[j].w, v[j].w, acc);
    }

    if (!isX) {
        #pragma unroll
        for (int o = 16; o > 0; o >>= 1)
            acc += __shfl_xor_sync(0xffffffffu, acc, o);
        if (lane == 0) g_csq[r] = acc;
    }
}

// ---------------------------------------------------------------------------
// Stage 1: bf16 HMMA GEMM (measured-best mainloop), 128x128x32 tiles.
// Epilogue: fp32 scores s = -2dot+csq -> per-64col-group (min, margin-mask).
// ---------------------------------------------------------------------------
__device__ __forceinline__ void cp16(uint32_t dst, const void* src) {
    asm volatile("cp.async.cg.shared.global [%0], [%1], 16;\n" :: "r"(dst), "l"(src));
}
__device__ __forceinline__ void ldsm4(uint32_t* r, uint32_t addr) {
    asm volatile("ldmatrix.sync.aligned.m8n8.x4.shared.b16 {%0,%1,%2,%3}, [%4];"
                 : "=r"(r[0]), "=r"(r[1]), "=r"(r[2]), "=r"(r[3]) : "r"(addr));
}
__device__ __forceinline__ void mma16816(float* c, const uint32_t* a, uint32_t b0, uint32_t b1) {
    asm volatile("mma.sync.aligned.m16n8k16.row.col.f32.bf16.bf16.f32 "
                 "{%0,%1,%2,%3}, {%4,%5,%6,%7}, {%8,%9}, {%0,%1,%2,%3};"
                 : "+f"(c[0]), "+f"(c[1]), "+f"(c[2]), "+f"(c[3])
                 : "r"(a[0]), "r"(a[1]), "r"(a[2]), "r"(a[3]), "r"(b0), "r"(b1));
}

#define TILE_HALF (BM * PAD_K)                 // bf16 elems per tile buffer
#define DSM_BYTES (4 * TILE_HALF * 2)          // 40960 B (2 bufs x (A+B))

__global__ __launch_bounds__(256, 2) void mma_score_kernel() {
    extern __shared__ __align__(128) char dsm[];
    __shared__ float s_csq[BN];

    const int tid  = threadIdx.x;
    const int warp = tid >> 5, lane = tid & 31;
    const int wm = warp >> 1, wn = warp & 1;
    const int m0 = blockIdx.y * BM;
    const int n0 = blockIdx.x * BN;

    float acc[2][8][4];
    #pragma unroll
    for (int i = 0; i < 2; i++)
        #pragma unroll
        for (int j = 0; j < 8; j++)
            #pragma unroll
            for (int k = 0; k < 4; k++) acc[i][j][k] = 0.f;

    const uint32_t sbase = (uint32_t)__cvta_generic_to_shared(dsm);
    uint32_t sA[2], sB[2];
    sA[0] = sbase;
    sA[1] = sbase + TILE_HALF * 2;
    sB[0] = sbase + 2 * TILE_HALF * 2;
    sB[1] = sbase + 3 * TILE_HALF * 2;

    if (tid < BN / 2)
        *(float2*)&s_csq[tid * 2] = *(const float2*)&g_csq[n0 + tid * 2];

    // tile loaders: thread -> row tid>>1, 32B half (tid&1)
    const int lr = tid >> 1;
    const int lc = (tid & 1) * 16;
    const uint32_t dOff = (uint32_t)(lr * PAD_K + lc) * 2;

    auto load_tile = [&](int buf, int k0) {
        const __nv_bfloat16* srcA = g_xb + (size_t)(m0 + lr) * DIM + k0 + lc;
        cp16(sA[buf] + dOff,      srcA);
        cp16(sA[buf] + dOff + 16, srcA + 8);
        const __nv_bfloat16* srcB = g_cb + (size_t)(n0 + lr) * DIM + k0 + lc;
        cp16(sB[buf] + dOff,      srcB);
        cp16(sB[buf] + dOff + 16, srcB + 8);
    };

    load_tile(0, 0);
    asm volatile("cp.async.commit_group;");
    asm volatile("cp.async.wait_group 0;");
    __syncthreads();

    // ldmatrix lane geometry
    const int a_row = (lane & 7) + ((lane >> 3) & 1) * 8;
    const int a_kof = (lane >> 4) * 8;
    const int b_row = (lane & 7) + (lane >> 4) * 8;
    const int b_kof = ((lane >> 3) & 1) * 8;

    #pragma unroll 1
    for (int kt = 0; kt < NITER; kt++) {
        const int buf = kt & 1;
        if (kt + 1 < NITER) {
            load_tile(buf ^ 1, (kt + 1) * BK);
            asm volatile("cp.async.commit_group;");
        }

        #pragma unroll
        for (int ks = 0; ks < BK; ks += 16) {
            uint32_t af[2][4];
            #pragma unroll
            for (int mi = 0; mi < 2; mi++) {
                uint32_t addr = sA[buf] +
                    (uint32_t)((wm * 32 + mi * 16 + a_row) * PAD_K + ks + a_kof) * 2;
                ldsm4(af[mi], addr);
            }
            #pragma unroll
            for (int nt = 0; nt < 4; nt++) {
                uint32_t bf[4];
                uint32_t addr = sB[buf] +
                    (uint32_t)((wn * 64 + nt * 16 + b_row) * PAD_K + ks + b_kof) * 2;
                ldsm4(bf, addr);
                #pragma unroll
                for (int mi = 0; mi < 2; mi++) {
                    mma16816(acc[mi][2 * nt + 0], af[mi], bf[0], bf[1]);
                    mma16816(acc[mi][2 * nt + 1], af[mi], bf[2], bf[3]);
                }
            }
        }

        asm volatile("cp.async.wait_group 0;");
        __syncthreads();
    }

    // ---- epilogue: per (row, 64-col group): fp32 min + margin bitmask ----
    const int grp = blockIdx.x * 2 + wn;
    #pragma unroll
    for (int mi = 0; mi < 2; mi++) {
        #pragma unroll
        for (int h = 0; h < 2; h++) {
            const int rl = wm * 32 + mi * 16 + h * 8 + (lane >> 2);  // local row
            float sc[16];
            float lmin = 3.4e38f;
            #pragma unroll
            for (int ni = 0; ni < 8; ni++) {
                const int cl = wn * 64 + ni * 8 + (lane & 3) * 2;    // local col
                const float s0 = fmaf(-2.f, acc[mi][ni][h * 2 + 0], s_csq[cl + 0]);
                const float s1 = fmaf(-2.f, acc[mi][ni][h * 2 + 1], s_csq[cl + 1]);
                sc[2 * ni + 0] = s0;
                sc[2 * ni + 1] = s1;
                lmin = fminf(lmin, fminf(s0, s1));
            }
            lmin = fminf(lmin, __shfl_xor_sync(0xffffffffu, lmin, 1));
            lmin = fminf(lmin, __shfl_xor_sync(0xffffffffu, lmin, 2));
            const float thr = lmin + MARGIN;
            unsigned long long m = 0ull;
            #pragma unroll
            for (int ni = 0; ni < 8; ni++) {
                const int bp = ni * 8 + (lane & 3) * 2;
                if (sc[2 * ni + 0] <= thr) m |= 1ull << bp;
                if (sc[2 * ni + 1] <= thr) m |= 1ull << (bp + 1);
            }
            m |= __shfl_xor_sync(0xffffffffu, m, 1);
            m |= __shfl_xor_sync(0xffffffffu, m, 2);
            if ((lane & 3) == 0) {
                const size_t o = (size_t)(m0 + rl) * NGRP + grp;
                g_tmin[o] = lmin;
                g_mask[o] = m;
            }
        }
    }
}

// ---------------------------------------------------------------------------
// Stage 2 (fused): warp-per-row candidate resolve + gather. x_sq computed
// locally from xv regs in the slow path. cnt==1 fast path; exact fp32
// rescore otherwise (reference-faithful fmaf(-2,dot,xs)+csq, lowest-index
// tie-break). Gather fused.
// ---------------------------------------------------------------------------
__global__ __launch_bounds__(256) void rescore_gather_kernel(
    const float* __restrict__ x, const float* __restrict__ cent,
    const float* __restrict__ table, const float* __restrict__ bias,
    float* __restrict__ out)
{
    __shared__ int s_cand[8][MAXCAND];
    __shared__ int s_cnt[8];

    const int w = threadIdx.x >> 5, lane = threadIdx.x & 31;
    const int r = blockIdx.x * 8 + w;

    if (lane == 0) s_cnt[w] = 0;
    __syncwarp();

    const float tmin = (lane < NGRP) ? g_tmin[(size_t)r * NGRP + lane] : 3.4e38f;
    float gmin = tmin;
    #pragma unroll
    for (int o = 16; o > 0; o >>= 1)
        gmin = fminf(gmin, __shfl_xor_sync(0xffffffffu, gmin, o));
    const float thr = gmin + MARGIN;

    if (lane < NGRP && tmin <= thr) {
        unsigned long long m = g_mask[(size_t)r * NGRP + lane];
        while (m) {
            const int b = __ffsll((long long)m) - 1;
            m &= m - 1;
            const int p = atomicAdd(&s_cnt[w], 1);
            if (p < MAXCAND) s_cand[w][p] = lane * 64 + b;
        }
    }
    __syncwarp();
    const int cnt = min(s_cnt[w], MAXCAND);

    int bidx;
    if (cnt == 1) {               // unique candidate within margin: exact winner
        bidx = s_cand[w][0];
    } else {
        // x row strided into regs: xv[j] = x[r][j*32 + lane] (coalesced per j)
        const float* xr = x + (size_t)r * DIM;
        float xv[32];
        #pragma unroll
        for (int j = 0; j < 32; j++) xv[j] = xr[j * 32 + lane];

        // x_sq from registers (order-robust; exact-path quantization dominates)
        float xs = 0.f;
        #pragma unroll
        for (int j = 0; j < 32; j++) xs = fmaf(xv[j], xv[j], xs);
        #pragma unroll
        for (int o = 16; o > 0; o >>= 1)
            xs += __shfl_xor_sync(0xffffffffu, xs, o);

        float best = 3.4e38f;
        bidx = NCENT;
        for (int ci = 0; ci < cnt; ci++) {
            const int c = s_cand[w][ci];
            const float* cr = cent + (size_t)c * DIM;
            float a = 0.f;
            #pragma unroll
            for (int j = 0; j < 32; j++)
                a = fmaf(xv[j], cr[j * 32 + lane], a);
            #pragma unroll
            for (int o = 16; o > 0; o >>= 1)
                a += __shfl_xor_sync(0xffffffffu, a, o);
            const float d = fmaf(-2.f, a, xs) + g_csq[c];
            if (d < best || (d == best && c < bidx)) { best = d; bidx = c; }
        }
    }

    // gather: out[r] = table[bidx] + bias (warp-coalesced float4 sweeps)
    const float4* src = (const float4*)(table + (size_t)bidx * DIM);
    const float4* bv  = (const float4*)bias;
    float4* dst = (float4*)(out + (size_t)r * DIM);
    #pragma unroll
    for (int j = 0; j < 8; j++) {
        const float4 a = src[j * 32 + lane];
        const float4 b = bv[j * 32 + lane];
        dst[j * 32 + lane] = make_float4(a.x + b.x, a.y + b.y, a.z + b.z, a.w + b.w);
    }
}

// ---------------------------------------------------------------------------
extern "C" void kernel_launch(void* const* d_in, const int* in_sizes, int n_in,
                              void* d_out, int out_size) {
    const float* x     = (const float*)d_in[0];  // [4,4096,1024]
    const float* cent  = (const float*)d_in[1];  // [1024,1024]
    const float* table = (const float*)d_in[2];  // [1024,1024]
    const float* bias  = (const float*)d_in[3];  // [1024]
    float* out = (float*)d_out;

    cudaFuncSetAttribute(mma_score_kernel,
                         cudaFuncAttributeMaxDynamicSharedMemorySize, DSM_BYTES);

    prep_kernel<<<(NROWS + NCENT) / 8, 256>>>(x, cent);
    mma_score_kernel<<<dim3(NCENT / BN, NROWS / BM), 256, DSM_BYTES>>>();
    rescore_gather_kernel<<<NROWS / 8, 256>>>(x, cent, table, bias, out);
}

// round 16
// speedup vs baseline: 1.4625x; 1.4625x over previous
#include <cuda_runtime.h>
#include <cuda_bf16.h>
#include <cstdint>

#define NROWS 16384
#define DIM   1024
#define NCENT 1024
#define MARGIN 0.35f

#define BM 128
#define BN 128
#define BK 32
#define PAD_K 40   // bf16 elems per smem row (80B stride -> conflict-free ldmatrix)
#define NITER (DIM / BK)
#define NGRP  (NCENT / 64)   // 16 col-groups of 64 per row
#define MAXCAND 64

// ---- scratch (device globals only; no runtime allocation allowed) ----
__device__ float              g_xsq[NROWS];
__device__ float              g_csq[NCENT];
__device__ float              g_tmin[(size_t)NROWS * NGRP];   // 1 MB
__device__ unsigned long long g_mask[(size_t)NROWS * NGRP];   // 2 MB
__device__ __nv_bfloat16      g_xb[(size_t)NROWS * DIM];      // 32 MB
__device__ __nv_bfloat16      g_cb[(size_t)NCENT * DIM];      //  2 MB

// ---------------------------------------------------------------------------
// Prep, warp-per-row: 8 rows per 256-thread block, no block barriers.
// Rows [0,NROWS) = x, [NROWS,NROWS+NCENT) = centroids.
// Exact fp32 sum-of-squares (warp butterfly) + bf16 conversion.
// ---------------------------------------------------------------------------
__global__ __launch_bounds__(256) void prep_kernel(
    const float* __restrict__ x, const float* __restrict__ c)
{
    const int w = threadIdx.x >> 5, lane = threadIdx.x & 31;
    const int row = blockIdx.x * 8 + w;
    const bool isX = (row < NROWS);
    const int r = isX ? row : (row - NROWS);
    const float4* src = (const float4*)((isX ? x : c) + (size_t)r * DIM);
    __nv_bfloat162* dst = (__nv_bfloat162*)((isX ? g_xb : g_cb) + (size_t)r * DIM);

    float acc = 0.f;
    #pragma unroll
    for (int j = 0; j < 8; j++) {
        const int e = j * 32 + lane;          // float4 index within row
        const float4 v = src[e];
        __nv_bfloat162 b01, b23;
        b01.x = __float2bfloat16(v.x); b01.y = __float2bfloat16(v.y);
        b23.x = __float2bfloat16(v.z); b23.y = __float2bfloat16(v.w);
        dst[e * 2 + 0] = b01;
        dst[e * 2 + 1] = b23;
        acc = fmaf(v.x, v.x, acc);
        acc = fmaf(v.y, v.y, acc);
        acc = fmaf(v.z, v.z, acc);
        acc = fmaf(v.w, v.w, acc);
    }
    #pragma unroll
    for (int o = 16; o > 0; o >>= 1)
        acc += __shfl_xor_sync(0xffffffffu, acc, o);

    if (lane == 0) {
        if (isX) g_xsq[r] = acc;
        else     g_csq[r] = acc;
    }
}

// ---------------------------------------------------------------------------
// Stage 1: bf16 HMMA GEMM (measured-best mainloop), 128x128x32 tiles.
// Epilogue: fp32 scores s = -2dot+csq -> per-64col-group (min, margin-mask).
// No score matrix is materialized.
// ---------------------------------------------------------------------------
__device__ __forceinline__ void cp16(uint32_t dst, const void* src) {
    asm volatile("cp.async.cg.shared.global [%0], [%1], 16;\n" :: "r"(dst), "l"(src));
}
__device__ __forceinline__ void ldsm4(uint32_t* r, uint32_t addr) {
    asm volatile("ldmatrix.sync.aligned.m8n8.x4.shared.b16 {%0,%1,%2,%3}, [%4];"
                 : "=r"(r[0]), "=r"(r[1]), "=r"(r[2]), "=r"(r[3]) : "r"(addr));
}
__device__ __forceinline__ void mma16816(float* c, const uint32_t* a, uint32_t b0, uint32_t b1) {
    asm volatile("mma.sync.aligned.m16n8k16.row.col.f32.bf16.bf16.f32 "
                 "{%0,%1,%2,%3}, {%4,%5,%6,%7}, {%8,%9}, {%0,%1,%2,%3};"
                 : "+f"(c[0]), "+f"(c[1]), "+f"(c[2]), "+f"(c[3])
                 : "r"(a[0]), "r"(a[1]), "r"(a[2]), "r"(a[3]), "r"(b0), "r"(b1));
}

#define TILE_HALF (BM * PAD_K)                 // bf16 elems per tile buffer
#define DSM_BYTES (4 * TILE_HALF * 2)          // 40960 B (2 bufs x (A+B))

__global__ __launch_bounds__(256, 2) void mma_score_kernel() {
    extern __shared__ __align__(128) char dsm[];
    __shared__ float s_csq[BN];

    const int tid  = threadIdx.x;
    const int warp = tid >> 5, lane = tid & 31;
    const int wm = warp >> 1, wn = warp & 1;
    const int m0 = blockIdx.y * BM;
    const int n0 = blockIdx.x * BN;

    float acc[2][8][4];
    #pragma unroll
    for (int i = 0; i < 2; i++)
        #pragma unroll
        for (int j = 0; j < 8; j++)
            #pragma unroll
            for (int k = 0; k < 4; k++) acc[i][j][k] = 0.f;

    const uint32_t sbase = (uint32_t)__cvta_generic_to_shared(dsm);
    uint32_t sA[2], sB[2];
    sA[0] = sbase;
    sA[1] = sbase + TILE_HALF * 2;
    sB[0] = sbase + 2 * TILE_HALF * 2;
    sB[1] = sbase + 3 * TILE_HALF * 2;

    if (tid < BN / 2)
        *(float2*)&s_csq[tid * 2] = *(const float2*)&g_csq[n0 + tid * 2];

    // tile loaders: thread -> row tid>>1, 32B half (tid&1)
    const int lr = tid >> 1;
    const int lc = (tid & 1) * 16;
    const uint32_t dOff = (uint32_t)(lr * PAD_K + lc) * 2;

    auto load_tile = [&](int buf, int k0) {
        const __nv_bfloat16* srcA = g_xb + (size_t)(m0 + lr) * DIM + k0 + lc;
        cp16(sA[buf] + dOff,      srcA);
        cp16(sA[buf] + dOff + 16, srcA + 8);
        const __nv_bfloat16* srcB = g_cb + (size_t)(n0 + lr) * DIM + k0 + lc;
        cp16(sB[buf] + dOff,      srcB);
        cp16(sB[buf] + dOff + 16, srcB + 8);
    };

    load_tile(0, 0);
    asm volatile("cp.async.commit_group;");
    asm volatile("cp.async.wait_group 0;");
    __syncthreads();

    // ldmatrix lane geometry
    const int a_row = (lane & 7) + ((lane >> 3) & 1) * 8;
    const int a_kof = (lane >> 4) * 8;
    const int b_row = (lane & 7) + (lane >> 4) * 8;
    const int b_kof = ((lane >> 3) & 1) * 8;

    #pragma unroll 1
    for (int kt = 0; kt < NITER; kt++) {
        const int buf = kt & 1;
        if (kt + 1 < NITER) {
            load_tile(buf ^ 1, (kt + 1) * BK);
            asm volatile("cp.async.commit_group;");
        }

        #pragma unroll
        for (int ks = 0; ks < BK; ks += 16) {
            uint32_t af[2][4];
            #pragma unroll
            for (int mi = 0; mi < 2; mi++) {
                uint32_t addr = sA[buf] +
                    (uint32_t)((wm * 32 + mi * 16 + a_row) * PAD_K + ks + a_kof) * 2;
                ldsm4(af[mi], addr);
            }
            #pragma unroll
            for (int nt = 0; nt < 4; nt++) {
                uint32_t bf[4];
                uint32_t addr = sB[buf] +
                    (uint32_t)((wn * 64 + nt * 16 + b_row) * PAD_K + ks + b_kof) * 2;
                ldsm4(bf, addr);
                #pragma unroll
                for (int mi = 0; mi < 2; mi++) {
                    mma16816(acc[mi][2 * nt + 0], af[mi], bf[0], bf[1]);
                    mma16816(acc[mi][2 * nt + 1], af[mi], bf[2], bf[3]);
                }
            }
        }

        asm volatile("cp.async.wait_group 0;");
        __syncthreads();
    }

    // ---- epilogue: per (row, 64-col group): fp32 min + margin bitmask ----
    // Warp wn covers group grp = blockIdx.x*2 + wn; 4 lanes per row.
    const int grp = blockIdx.x * 2 + wn;
    #pragma unroll
    for (int mi = 0; mi < 2; mi++) {
        #pragma unroll
        for (int h = 0; h < 2; h++) {
            const int rl = wm * 32 + mi * 16 + h * 8 + (lane >> 2);  // local row
            float sc[16];
            float lmin = 3.4e38f;
            #pragma unroll
            for (int ni = 0; ni < 8; ni++) {
                const int cl = wn * 64 + ni * 8 + (lane & 3) * 2;    // local col
                const float s0 = fmaf(-2.f, acc[mi][ni][h * 2 + 0], s_csq[cl + 0]);
                const float s1 = fmaf(-2.f, acc[mi][ni][h * 2 + 1], s_csq[cl + 1]);
                sc[2 * ni + 0] = s0;
                sc[2 * ni + 1] = s1;
                lmin = fminf(lmin, fminf(s0, s1));
            }
            // group min across the 4 lanes of this row
            lmin = fminf(lmin, __shfl_xor_sync(0xffffffffu, lmin, 1));
            lmin = fminf(lmin, __shfl_xor_sync(0xffffffffu, lmin, 2));
            // margin mask (fp32 scores, local threshold — superset-safe)
            const float thr = lmin + MARGIN;
            unsigned long long m = 0ull;
            #pragma unroll
            for (int ni = 0; ni < 8; ni++) {
                const int bp = ni * 8 + (lane & 3) * 2;  // bit pos within group
                if (sc[2 * ni + 0] <= thr) m |= 1ull << bp;
                if (sc[2 * ni + 1] <= thr) m |= 1ull << (bp + 1);
            }
            m |= __shfl_xor_sync(0xffffffffu, m, 1);
            m |= __shfl_xor_sync(0xffffffffu, m, 2);
            if ((lane & 3) == 0) {
                const size_t o = (size_t)(m0 + rl) * NGRP + grp;
                g_tmin[o] = lmin;
                g_mask[o] = m;
            }
        }
    }
}

// ---------------------------------------------------------------------------
// Stage 2 (fused): warp-per-row candidate resolve + gather. 8 rows per block,
// no block barriers. gmin from 16 group-mins; decode masks of qualifying
// groups; cnt==1 fast path; exact fp32 rescore otherwise (reference-faithful
// fmaf(-2,dot,xsq)+csq, lowest-index tie-break). Gather fused.
// ---------------------------------------------------------------------------
__global__ __launch_bounds__(256) void rescore_gather_kernel(
    const float* __restrict__ x, const float* __restrict__ cent,
    const float* __restrict__ table, const float* __restrict__ bias,
    float* __restrict__ out)
{
    __shared__ int s_cand[8][MAXCAND];
    __shared__ int s_cnt[8];

    const int w = threadIdx.x >> 5, lane = threadIdx.x & 31;
    const int r = blockIdx.x * 8 + w;

    if (lane == 0) s_cnt[w] = 0;
    __syncwarp();

    const float tmin = (lane < NGRP) ? g_tmin[(size_t)r * NGRP + lane] : 3.4e38f;
    float gmin = tmin;
    #pragma unroll
    for (int o = 16; o > 0; o >>= 1)
        gmin = fminf(gmin, __shfl_xor_sync(0xffffffffu, gmin, o));
    const float thr = gmin + MARGIN;

    if (lane < NGRP && tmin <= thr) {
        unsigned long long m = g_mask[(size_t)r * NGRP + lane];
        while (m) {
            const int b = __ffsll((long long)m) - 1;
            m &= m - 1;
            const int p = atomicAdd(&s_cnt[w], 1);
            if (p < MAXCAND) s_cand[w][p] = lane * 64 + b;
        }
    }
    __syncwarp();
    const int cnt = min(s_cnt[w], MAXCAND);

    int bidx;
    if (cnt == 1) {               // unique candidate within margin: exact winner
        bidx = s_cand[w][0];
    } else {
        // x row strided into regs: xv[j] = x[r][j*32 + lane] (coalesced per j)
        const float* xr = x + (size_t)r * DIM;
        float xv[32];
        #pragma unroll
        for (int j = 0; j < 32; j++) xv[j] = xr[j * 32 + lane];
        const float xs = g_xsq[r];

        float best = 3.4e38f;
        bidx = NCENT;
        for (int ci = 0; ci < cnt; ci++) {
            const int c = s_cand[w][ci];
            const float* cr = cent + (size_t)c * DIM;
            float a = 0.f;
            #pragma unroll
            for (int j = 0; j < 32; j++)
                a = fmaf(xv[j], cr[j * 32 + lane], a);
            #pragma unroll
            for (int o = 16; o > 0; o >>= 1)
                a += __shfl_xor_sync(0xffffffffu, a, o);
            const float d = fmaf(-2.f, a, xs) + g_csq[c];
            if (d < best || (d == best && c < bidx)) { best = d; bidx = c; }
        }
    }

    // gather: out[r] = table[bidx] + bias (warp-coalesced float4 sweeps)
    const float4* src = (const float4*)(table + (size_t)bidx * DIM);
    const float4* bv  = (const float4*)bias;
    float4* dst = (float4*)(out + (size_t)r * DIM);
    #pragma unroll
    for (int j = 0; j < 8; j++) {
        const float4 a = src[j * 32 + lane];
        const float4 b = bv[j * 32 + lane];
        dst[j * 32 + lane] = make_float4(a.x + b.x, a.y + b.y, a.z + b.z, a.w + b.w);
    }
}

// ---------------------------------------------------------------------------
extern "C" void kernel_launch(void* const* d_in, const int* in_sizes, int n_in,
                              void* d_out, int out_size) {
    const float* x     = (const float*)d_in[0];  // [4,4096,1024]
    const float* cent  = (const float*)d_in[1];  // [1024,1024]
    const float* table = (const float*)d_in[2];  // [1024,1024]
    const float* bias  = (const float*)d_in[3];  // [1024]
    float* out = (float*)d_out;

    cudaFuncSetAttribute(mma_score_kernel,
                         cudaFuncAttributeMaxDynamicSharedMemorySize, DSM_BYTES);

    prep_kernel<<<(NROWS + NCENT) / 8, 256>>>(x, cent);
    mma_score_kernel<<<dim3(NCENT / BN, NROWS / BM), 256, DSM_BYTES>>>();
    rescore_gather_kernel<<<NROWS / 8, 256>>>(x, cent, table, bias, out);
}